// round 6
// baseline (speedup 1.0000x reference)
#include <cuda_runtime.h>
#include <cuda_fp16.h>

#define H 512
#define W 512
#define NP 24                 // 8*3 planes
#define WXROWS 502
#define WXCOLS 503
#define WYROWS 503
#define WYCOLS 502
#define LWIN (WXROWS*WXCOLS)  // 252506 per plane
#define NBANDS 12
#define BAND 43               // 12*43 = 516 >= 512
#define NBLK (NBANDS*NP)      // 288

__device__ float g_part[NBLK * 3];   // per-block partials: gx, gy, norm

__device__ __forceinline__ float warp_red(float v) {
    #pragma unroll
    for (int o = 16; o; o >>= 1) v += __shfl_down_sync(0xffffffffu, v, o);
    return v;
}

struct Smem {
    __half2 ringX[10 * 512];   // 20480 B
    __half2 ringY[10 * 512];   // 20480 B
    __half2 VxS[2][512];       //  4096 B (double buffered by iter parity)
    __half2 VyS[2][512];       //  4096 B
    __half2 Ybuf[4][512];      //  8192 B (Y window rows, ring by row&3)
    float   edge[2][16][3];    //   384 B (warp-boundary row values)
    float   red[96];           //   384 B
};
#define SMEM_BYTES ((int)sizeof(Smem))

__global__ void __launch_bounds__(512, 2) win_kernel(
        const float* __restrict__ Al,
        const float* __restrict__ Ar,
        const float* __restrict__ Ai) {
    extern __shared__ unsigned char smraw[];
    Smem* sm = (Smem*)smraw;

    const int c    = threadIdx.x;
    const int lane = c & 31, w = c >> 5;
    const int p    = blockIdx.y;
    const int R0   = blockIdx.x * BAND;
    const int R1   = min(R0 + BAND, H);
    const int rend = min(R1 + 9, H - 1);

    const __half2 hz = __floats2half2_rn(0.f, 0.f);
    #pragma unroll
    for (int k = c; k < 10 * 512; k += 512) { sm->ringX[k] = hz; sm->ringY[k] = hz; }

    const size_t pb = (size_t)p * H * W;
    const float* Bl = Al + pb;
    const float* Br = Ar + pb;
    const float* Bi = Ai + pb;

    // register pipeline: cur=row r, nxt=row r+1, n2=row r+2 (in flight)
    float cl = Bl[R0 * W + c], cr = Br[R0 * W + c], ci = Bi[R0 * W + c];
    float nl = Bl[(R0 + 1) * W + c], nr = Br[(R0 + 1) * W + c], ni = Bi[(R0 + 1) * W + c];
    float n2l = 0.f, n2r = 0.f, n2i = 0.f;
    float pl = 0.f, pr = 0.f, pv = 0.f;
    if (lane == 0) { sm->edge[0][w][0] = cl; sm->edge[0][w][1] = cr; sm->edge[0][w][2] = ci; }

    float Vxn = 0.f, Vxd = 0.f, Vyn = 0.f, Vyd = 0.f;
    float gxacc = 0.f, gyacc = 0.f, normacc = 0.f;
    float xn_pend = 0.f, xd_pend = 0.f;
    __syncthreads();

    for (int r = R0; r <= rend; ++r) {
        const int eb = (r - R0) & 1;

        // ---- P1: prefetch row r+2 (consumed 2 barriers later) ----
        const int r2 = r + 2;
        if (r2 <= rend) {
            n2l = Bl[r2 * W + c]; n2r = Br[r2 * W + c]; n2i = Bi[r2 * W + c];
        }
        // publish next row's warp-edge values (read next iteration)
        if (lane == 0) {
            sm->edge[eb ^ 1][w][0] = nl; sm->edge[eb ^ 1][w][1] = nr; sm->edge[eb ^ 1][w][2] = ni;
        }

        // ---- gy row r (neighbor c+1 via shuffle; warp edge from smem) ----
        float rl = __shfl_down_sync(0xffffffffu, cl, 1);
        float rr = __shfl_down_sync(0xffffffffu, cr, 1);
        float rv = __shfl_down_sync(0xffffffffu, ci, 1);
        float uy = 0.f, dy = 0.f;
        if (c < W - 1) {
            if (lane == 31) {
                rl = sm->edge[eb][w + 1][0];
                rr = sm->edge[eb][w + 1][1];
                rv = sm->edge[eb][w + 1][2];
            }
            float gl = rl - cl, gr = rr - cr, gi = rv - ci;
            uy = fabsf(gl) + fabsf(gr);
            dy = fabsf(gi);
            if (r < R1) gyacc += fabsf(gl + gr - gi);
        }
        {
            int slot = ((r - R0) % 10) * 512 + c;
            __half2 h = __floats2half2_rn(uy, dy);
            __half2 old = sm->ringY[slot];
            sm->ringY[slot] = h;
            float2 hf = __half22float2(h), of = __half22float2(old);
            Vyn += hf.x - of.x;  Vyd += hf.y - of.y;
            sm->VyS[eb][c] = __floats2half2_rn(Vyn, Vyd);
        }
        // ---- gx row g = r-1 (pure registers) ----
        if (r > R0) {
            float gl = cl - pl, gr = cr - pr, gi = ci - pv;
            float ux = fabsf(gl) + fabsf(gr), dx = fabsf(gi);
            int g = r - 1;
            if (g < R1) gxacc += fabsf(gl + gr - gi);
            int slot = ((g - R0) % 10) * 512 + c;
            __half2 h = __floats2half2_rn(ux, dx);
            __half2 old = sm->ringX[slot];
            sm->ringX[slot] = h;
            float2 hf = __half22float2(h), of = __half22float2(old);
            Vxn += hf.x - of.x;  Vxd += hf.y - of.y;
            sm->VxS[eb][c] = __floats2half2_rn(Vxn, Vxd);
        }

        __syncthreads();   // single barrier: V publish -> box reads; Ybuf/edge reuse

        // ---- P2: ratio for pending X row rxp = r-11 (Y rows r-11, r-10 visible) ----
        {
            const int rxp = r - 11;
            if (rxp >= R0 && rxp < R1 && rxp < WXROWS && c < WXCOLS) {
                int t = rxp + c;
                int ry = rxp, cy = t;
                if (t >= WYCOLS) { ry = rxp + 1; cy = t - WYCOLS; }
                float2 yv = __half22float2(sm->Ybuf[ry & 3][cy]);
                normacc += __fdividef(xn_pend + yv.x, xd_pend + yv.y + 1e-4f);
            }
        }
        // ---- horizontal 10-wide box sums ----
        const int ry = r - 9;
        if (ry >= R0 && ry <= R1 && ry < WYROWS && c < WYCOLS) {
            float sn = 0.f, sd = 0.f;
            #pragma unroll
            for (int d = 0; d < 10; ++d) {
                float2 v = __half22float2(sm->VyS[eb][c + d]);
                sn += v.x; sd += v.y;
            }
            sm->Ybuf[ry & 3][c] = __floats2half2_rn(sn, sd);
        }
        const int rx = r - 10;
        if (rx >= R0 && rx < R1 && rx < WXROWS && c < WXCOLS) {
            float sn = 0.f, sd = 0.f;
            #pragma unroll
            for (int d = 0; d < 10; ++d) {
                float2 v = __half22float2(sm->VxS[eb][c + d]);
                sn += v.x; sd += v.y;
            }
            xn_pend = sn; xd_pend = sd;   // consumed next iteration / epilogue
        }

        // rotate register pipeline
        pl = cl; pr = cr; pv = ci;
        cl = nl; cr = nr; ci = ni;
        nl = n2l; nr = n2r; ni = n2i;
    }

    // ---- epilogue: last pending X row (rxp = rend-10) ----
    __syncthreads();
    {
        const int rxp = rend - 10;
        if (rxp >= R0 && rxp < R1 && rxp < WXROWS && c < WXCOLS) {
            int t = rxp + c;
            int ry = rxp, cy = t;
            if (t >= WYCOLS) { ry = rxp + 1; cy = t - WYCOLS; }
            float2 yv = __half22float2(sm->Ybuf[ry & 3][cy]);
            normacc += __fdividef(xn_pend + yv.x, xd_pend + yv.y + 1e-4f);
        }
    }

    // ---- block reduce: gx, gy, norm -> per-block partials (no atomics) ----
    __syncthreads();
    float vx = warp_red(gxacc);
    float vy = warp_red(gyacc);
    float vn = warp_red(normacc);
    int wid = c >> 5, lid = c & 31;
    if (lid == 0) { sm->red[wid] = vx; sm->red[32 + wid] = vy; sm->red[64 + wid] = vn; }
    __syncthreads();
    if (wid == 0) {
        float a = (lid < 16) ? sm->red[lid]      : 0.f;
        float b = (lid < 16) ? sm->red[32 + lid] : 0.f;
        float n = (lid < 16) ? sm->red[64 + lid] : 0.f;
        a = warp_red(a);
        b = warp_red(b);
        n = warp_red(n);
        if (lid == 0) {
            int bid = blockIdx.y * NBANDS + blockIdx.x;
            g_part[bid * 3 + 0] = a;
            g_part[bid * 3 + 1] = b;
            g_part[bid * 3 + 2] = n;
        }
    }
}

__global__ void final_kernel(float* __restrict__ out) {
    const int t = threadIdx.x;   // 32 threads
    double a = 0.0, b = 0.0, n = 0.0;
    for (int i = t; i < NBLK; i += 32) {
        a += (double)g_part[i * 3 + 0];
        b += (double)g_part[i * 3 + 1];
        n += (double)g_part[i * 3 + 2];
    }
    #pragma unroll
    for (int o = 16; o; o >>= 1) {
        a += __shfl_down_sync(0xffffffffu, a, o);
        b += __shfl_down_sync(0xffffffffu, b, o);
        n += __shfl_down_sync(0xffffffffu, n, o);
    }
    if (t == 0) {
        double norm_loss = n / 6060144.0;                 // 24 * 252506
        double grad_loss = a / 6279168.0 + b / 6279168.0; // 24 * 511 * 512
        out[0] = (float)(norm_loss * 1e-4 + grad_loss);
    }
}

extern "C" void kernel_launch(void* const* d_in, const int* in_sizes, int n_in,
                              void* d_out, int out_size) {
    const float* l  = (const float*)d_in[0];
    const float* r  = (const float*)d_in[1];
    const float* ii = (const float*)d_in[2];
    float* out = (float*)d_out;

    cudaFuncSetAttribute(win_kernel,
                         cudaFuncAttributeMaxDynamicSharedMemorySize, SMEM_BYTES);

    dim3 g1(NBANDS, NP);
    win_kernel<<<g1, 512, SMEM_BYTES>>>(l, r, ii);
    final_kernel<<<1, 32>>>(out);
}

// round 8
// speedup vs baseline: 1.0512x; 1.0512x over previous
#include <cuda_runtime.h>
#include <cuda_fp16.h>

#define H 512
#define W 512
#define NP 24                 // 8*3 planes
#define WXROWS 502
#define WXCOLS 503
#define WYROWS 503
#define WYCOLS 502
#define NBANDS 12
#define BAND 43               // 12*43 = 516 >= 512
#define NBLK (NBANDS*NP)      // 288

__device__ float        g_part[NBLK * 3];   // per-block partials: gx, gy, norm
__device__ unsigned int g_count = 0;        // finished-block counter (self-resetting)

__device__ __forceinline__ float warp_red(float v) {
    #pragma unroll
    for (int o = 16; o; o >>= 1) v += __shfl_down_sync(0xffffffffu, v, o);
    return v;
}

struct Smem {
    __half2 ringX[10 * 512];   // 20480 B
    __half2 ringY[10 * 512];   // 20480 B
    uint2   Vpack[2][512];     //  8192 B  (.x = half2(Vxn,Vxd), .y = half2(Vyn,Vyd))
    __half2 Ybuf[4][512];      //  8192 B  (Y window rows, ring by row&3)
    float   edge[2][16][3];    //   384 B  (warp-boundary row values)
    float   red[96];           //   384 B
    int     is_last;
};
#define SMEM_BYTES ((int)sizeof(Smem))

__global__ void __launch_bounds__(512, 2) win_kernel(
        const float* __restrict__ Al,
        const float* __restrict__ Ar,
        const float* __restrict__ Ai,
        float* __restrict__ out) {
    extern __shared__ unsigned char smraw[];
    Smem* sm = (Smem*)smraw;

    const int c    = threadIdx.x;
    const int lane = c & 31, w = c >> 5;
    const int p    = blockIdx.y;
    const int R0   = blockIdx.x * BAND;
    const int R1   = min(R0 + BAND, H);
    const int rend = min(R1 + 9, H - 1);

    const __half2 hz = __floats2half2_rn(0.f, 0.f);
    #pragma unroll
    for (int k = c; k < 10 * 512; k += 512) { sm->ringX[k] = hz; sm->ringY[k] = hz; }

    const size_t pb = (size_t)p * H * W;
    const float* Bl = Al + pb;
    const float* Br = Ar + pb;
    const float* Bi = Ai + pb;

    // register pipeline: cur=row r, nxt=row r+1, n2=row r+2 (in flight)
    float cl = Bl[R0 * W + c], cr = Br[R0 * W + c], ci = Bi[R0 * W + c];
    float nl = Bl[(R0 + 1) * W + c], nr = Br[(R0 + 1) * W + c], ni = Bi[(R0 + 1) * W + c];
    float n2l = 0.f, n2r = 0.f, n2i = 0.f;
    float pl = 0.f, pr = 0.f, pv = 0.f;
    if (lane == 0) { sm->edge[0][w][0] = cl; sm->edge[0][w][1] = cr; sm->edge[0][w][2] = ci; }

    float Vxn = 0.f, Vxd = 0.f, Vyn = 0.f, Vyd = 0.f;
    float gxacc = 0.f, gyacc = 0.f, normacc = 0.f;
    float xn_pend = 0.f, xd_pend = 0.f;
    __syncthreads();

    for (int r = R0; r <= rend; ++r) {
        const int eb = (r - R0) & 1;

        // prefetch row r+2 (consumed 2 barriers later)
        const int r2 = r + 2;
        if (r2 <= rend) {
            n2l = Bl[r2 * W + c]; n2r = Br[r2 * W + c]; n2i = Bi[r2 * W + c];
        }
        // publish next row's warp-edge values (read next iteration)
        if (lane == 0) {
            sm->edge[eb ^ 1][w][0] = nl; sm->edge[eb ^ 1][w][1] = nr; sm->edge[eb ^ 1][w][2] = ni;
        }

        // ---- gy row r (neighbor c+1 via shuffle; warp edge from smem) ----
        float rl = __shfl_down_sync(0xffffffffu, cl, 1);
        float rr = __shfl_down_sync(0xffffffffu, cr, 1);
        float rv = __shfl_down_sync(0xffffffffu, ci, 1);
        float uy = 0.f, dy = 0.f;
        if (c < W - 1) {
            if (lane == 31) {
                rl = sm->edge[eb][w + 1][0];
                rr = sm->edge[eb][w + 1][1];
                rv = sm->edge[eb][w + 1][2];
            }
            float gl = rl - cl, gr = rr - cr, gi = rv - ci;
            uy = fabsf(gl) + fabsf(gr);
            dy = fabsf(gi);
            if (r < R1) gyacc += fabsf(gl + gr - gi);
        }
        {
            int slot = ((r - R0) % 10) * 512 + c;
            __half2 h = __floats2half2_rn(uy, dy);
            __half2 old = sm->ringY[slot];
            sm->ringY[slot] = h;
            float2 hf = __half22float2(h), of = __half22float2(old);
            Vyn += hf.x - of.x;  Vyd += hf.y - of.y;
        }
        // ---- gx row g = r-1 (pure registers) ----
        if (r > R0) {
            float gl = cl - pl, gr = cr - pr, gi = ci - pv;
            float ux = fabsf(gl) + fabsf(gr), dx = fabsf(gi);
            int g = r - 1;
            if (g < R1) gxacc += fabsf(gl + gr - gi);
            int slot = ((g - R0) % 10) * 512 + c;
            __half2 h = __floats2half2_rn(ux, dx);
            __half2 old = sm->ringX[slot];
            sm->ringX[slot] = h;
            float2 hf = __half22float2(h), of = __half22float2(old);
            Vxn += hf.x - of.x;  Vxd += hf.y - of.y;
        }
        // single packed V publish (X & Y share the same read range below)
        {
            __half2 hx = __floats2half2_rn(Vxn, Vxd);
            __half2 hy = __floats2half2_rn(Vyn, Vyd);
            uint2 u;
            u.x = *(const unsigned int*)&hx;
            u.y = *(const unsigned int*)&hy;
            sm->Vpack[eb][c] = u;
        }

        __syncthreads();   // V publish -> box reads; Ybuf/edge reuse

        // ---- ratio for pending X row rxp = r-11 (Y rows r-11, r-10 visible) ----
        {
            const int rxp = r - 11;
            if (rxp >= R0 && rxp < R1 && rxp < WXROWS && c < WXCOLS) {
                int t = rxp + c;
                int ry = rxp, cy = t;
                if (t >= WYCOLS) { ry = rxp + 1; cy = t - WYCOLS; }
                float2 yv = __half22float2(sm->Ybuf[ry & 3][cy]);
                normacc += __fdividef(xn_pend + yv.x, xd_pend + yv.y + 1e-4f);
            }
        }
        // ---- fused horizontal 10-wide box sums (X and Y in one pass) ----
        const int ry = r - 9;
        const int rx = r - 10;
        const bool doY = (ry >= R0 && ry <= R1 && ry < WYROWS && c < WYCOLS);
        const bool doX = (rx >= R0 && rx < R1 && rx < WXROWS && c < WXCOLS);
        if (doY || doX) {
            float sxn = 0.f, sxd = 0.f, syn = 0.f, syd = 0.f;
            #pragma unroll
            for (int d = 0; d < 10; ++d) {
                uint2 u = sm->Vpack[eb][c + d];
                float2 xv = __half22float2(*(const __half2*)&u.x);
                float2 yv = __half22float2(*(const __half2*)&u.y);
                sxn += xv.x; sxd += xv.y;
                syn += yv.x; syd += yv.y;
            }
            if (doY) sm->Ybuf[ry & 3][c] = __floats2half2_rn(syn, syd);
            if (doX) { xn_pend = sxn; xd_pend = sxd; }
        }

        // rotate register pipeline
        pl = cl; pr = cr; pv = ci;
        cl = nl; cr = nr; ci = ni;
        nl = n2l; nr = n2r; ni = n2i;
    }

    // ---- epilogue: last pending X row (rxp = rend-10) ----
    __syncthreads();
    {
        const int rxp = rend - 10;
        if (rxp >= R0 && rxp < R1 && rxp < WXROWS && c < WXCOLS) {
            int t = rxp + c;
            int ry = rxp, cy = t;
            if (t >= WYCOLS) { ry = rxp + 1; cy = t - WYCOLS; }
            float2 yv = __half22float2(sm->Ybuf[ry & 3][cy]);
            normacc += __fdividef(xn_pend + yv.x, xd_pend + yv.y + 1e-4f);
        }
    }

    // ---- block reduce: gx, gy, norm -> per-block partials ----
    __syncthreads();
    float vx = warp_red(gxacc);
    float vy = warp_red(gyacc);
    float vn = warp_red(normacc);
    if (lane == 0) { sm->red[w] = vx; sm->red[32 + w] = vy; sm->red[64 + w] = vn; }
    __syncthreads();
    if (w == 0) {
        float a = (lane < 16) ? sm->red[lane]      : 0.f;
        float b = (lane < 16) ? sm->red[32 + lane] : 0.f;
        float n = (lane < 16) ? sm->red[64 + lane] : 0.f;
        a = warp_red(a);
        b = warp_red(b);
        n = warp_red(n);
        if (lane == 0) {
            int bid = blockIdx.y * NBANDS + blockIdx.x;
            g_part[bid * 3 + 0] = a;
            g_part[bid * 3 + 1] = b;
            g_part[bid * 3 + 2] = n;
            __threadfence();
            unsigned int old = atomicAdd(&g_count, 1u);
            sm->is_last = (old == NBLK - 1) ? 1 : 0;
        }
    }
    __syncthreads();

    // ---- last block finishes the reduction (threadfence-reduction pattern) ----
    if (sm->is_last && w == 0) {
        __threadfence();
        double a = 0.0, b = 0.0, n = 0.0;
        for (int i = lane; i < NBLK; i += 32) {
            a += (double)g_part[i * 3 + 0];
            b += (double)g_part[i * 3 + 1];
            n += (double)g_part[i * 3 + 2];
        }
        #pragma unroll
        for (int o = 16; o; o >>= 1) {
            a += __shfl_down_sync(0xffffffffu, a, o);
            b += __shfl_down_sync(0xffffffffu, b, o);
            n += __shfl_down_sync(0xffffffffu, n, o);
        }
        if (lane == 0) {
            double norm_loss = n / 6060144.0;                 // 24 * 252506
            double grad_loss = a / 6279168.0 + b / 6279168.0; // 24 * 511 * 512
            out[0] = (float)(norm_loss * 1e-4 + grad_loss);
            g_count = 0;   // reset for next graph replay
        }
    }
}

extern "C" void kernel_launch(void* const* d_in, const int* in_sizes, int n_in,
                              void* d_out, int out_size) {
    const float* l  = (const float*)d_in[0];
    const float* r  = (const float*)d_in[1];
    const float* ii = (const float*)d_in[2];
    float* out = (float*)d_out;

    cudaFuncSetAttribute(win_kernel,
                         cudaFuncAttributeMaxDynamicSharedMemorySize, SMEM_BYTES);

    dim3 g1(NBANDS, NP);
    win_kernel<<<g1, 512, SMEM_BYTES>>>(l, r, ii, out);
}